// round 11
// baseline (speedup 1.0000x reference)
#include <cuda_runtime.h>
#include <cuda_bf16.h>

#define CCONST 7.1998226
#define THREADS 256
#define MAXB 64

__device__ double g_sum[MAXB];           // zero at load; reset by finalize each run
__device__ unsigned int g_done = 0;      // completion ticket (atomicInc wraps)

template <int NC>
__global__ __launch_bounds__(THREADS, 6)
void coulomb_occ6(const float* __restrict__ dij,
                  const float* __restrict__ q,
                  float* __restrict__ out,
                  int Nrt, int B, unsigned int totalBlocks) {
    const int N   = (NC > 0) ? NC : Nrt;
    const int b   = blockIdx.y;
    const int bpb = gridDim.x;
    const int tid = threadIdx.x;
    const int Tb  = N >> 1;              // 2-row tiles per batch

    const float* qb = q + (size_t)b * N;

    // fixed column ownership for the whole block lifetime (8 cols/thread)
    const int j0 = tid * 8;
    const float4 qa = __ldg((const float4*)(qb + j0));
    const float4 qc = __ldg((const float4*)(qb + j0 + 4));

    double acc = 0.0;

    for (int rg = blockIdx.x; rg < Tb; rg += bpb) {
        const int row0 = rg << 1;
        const float* base = dij + ((size_t)b * N + row0) * (size_t)N + j0;

        const float qi0 = __ldg(qb + row0);
        const float qi1 = __ldg(qb + row0 + 1);

        // 4 independent float4 loads front-batched (2 rows x 2)
        float4 da0 = __ldcs((const float4*)(base));
        float4 dc0 = __ldcs((const float4*)(base) + 1);
        float4 da1 = __ldcs((const float4*)(base + (size_t)N));
        float4 dc1 = __ldcs((const float4*)(base + (size_t)N) + 1);

        float l0 = __fdividef(qa.x, da0.x) + __fdividef(qa.y, da0.y)
                 + __fdividef(qa.z, da0.z) + __fdividef(qa.w, da0.w)
                 + __fdividef(qc.x, dc0.x) + __fdividef(qc.y, dc0.y)
                 + __fdividef(qc.z, dc0.z) + __fdividef(qc.w, dc0.w);

        float l1 = __fdividef(qa.x, da1.x) + __fdividef(qa.y, da1.y)
                 + __fdividef(qa.z, da1.z) + __fdividef(qa.w, da1.w)
                 + __fdividef(qc.x, dc1.x) + __fdividef(qc.y, dc1.y)
                 + __fdividef(qc.z, dc1.z) + __fdividef(qc.w, dc1.w);

        // promote per tile (fp64): 2 DFMA per tile, off the load path
        acc = fma((double)qi0, (double)l0, acc);
        acc = fma((double)qi1, (double)l1, acc);
    }

    // block reduce (fp64)
    #pragma unroll
    for (int off = 16; off; off >>= 1)
        acc += __shfl_down_sync(0xffffffffu, acc, off);

    __shared__ double sm[THREADS / 32];
    __shared__ bool is_last;
    if ((tid & 31) == 0) sm[tid >> 5] = acc;
    __syncthreads();

    if (tid < 32) {
        double v = (tid < THREADS / 32) ? sm[tid] : 0.0;
        #pragma unroll
        for (int off = 4; off; off >>= 1)
            v += __shfl_down_sync(0xffffffffu, v, off);
        if (tid == 0) {
            atomicAdd(&g_sum[b], v);
            __threadfence();
            unsigned int ticket = atomicInc(&g_done, totalBlocks - 1);
            is_last = (ticket == totalBlocks - 1);
        }
    }
    __syncthreads();

    if (is_last && tid < B) {
        double total = atomicAdd(&g_sum[tid], 0.0);   // coherent read
        out[tid] = (float)(CCONST * total);
        g_sum[tid] = 0.0;                             // reset for next replay
    }
}

extern "C" void kernel_launch(void* const* d_in, const int* in_sizes, int n_in,
                              void* d_out, int out_size) {
    // Identify inputs by element count: largest = d_ij [B,N,N]; q = [B,N].
    int di = 0;
    for (int i = 1; i < n_in; i++)
        if (in_sizes[i] > in_sizes[di]) di = i;
    const float* dij = (const float*)d_in[di];

    const long long B = (out_size > 0) ? out_size : 16;
    int qi = (di == 0 && n_in > 1) ? 1 : 0;
    for (int i = 0; i < n_in; i++) {
        if (i == di) continue;
        long long nq = in_sizes[i];
        long long Nc = nq / B;
        if (Nc > 0 && B * Nc * Nc == (long long)in_sizes[di]) { qi = i; break; }
    }
    const float* q = (const float*)d_in[qi];

    const int N = (int)((long long)in_sizes[qi] / B);   // 2048

    int sm_count = 148;
    cudaDeviceGetAttribute(&sm_count, cudaDevAttrMultiProcessorCount, 0);

    // 6 CTAs/SM total, partitioned per batch
    int bpb = (sm_count * 6) / (int)B;                  // 152*6/16 = 57
    if (bpb < 1) bpb = 1;
    const int Tb = N >> 1;
    if (bpb > Tb) bpb = Tb;

    const unsigned int totalBlocks = (unsigned int)(bpb * B);
    dim3 grid(bpb, (unsigned)B);

    if (N == 2048)
        coulomb_occ6<2048><<<grid, THREADS>>>(dij, q, (float*)d_out, N, (int)B, totalBlocks);
    else
        coulomb_occ6<0><<<grid, THREADS>>>(dij, q, (float*)d_out, N, (int)B, totalBlocks);
}

// round 12
// speedup vs baseline: 1.3212x; 1.3212x over previous
#include <cuda_runtime.h>
#include <cuda_bf16.h>

#define CCONST 7.1998226
#define RPB 8          // rows per tile
#define THREADS 256
#define MAXB 64

__device__ double g_sum[MAXB];           // zero at load; reset by finalize each run
__device__ unsigned int g_done = 0;      // completion ticket (atomicInc wraps)

__global__ __launch_bounds__(THREADS, 4)
void coulomb_coal(const float* __restrict__ dij,
                  const float* __restrict__ q,
                  float* __restrict__ out,
                  int N, int B, unsigned int totalBlocks) {
    const int b   = blockIdx.y;
    const int bpb = gridDim.x;
    const int tid = threadIdx.x;
    const int Tb  = N / RPB;
    const int half4 = N >> 3;            // float4 index of second column half (N/2 floats)

    const float* qb = q + (size_t)b * N;
    const float4* q4 = (const float4*)qb;

    // split column ownership: cols [4t,4t+4) and [N/2+4t, N/2+4t+4)
    // -> every LDG.128 is warp-contiguous 512B (4 full lines, 4 wavefronts)
    const float4 qa = __ldg(q4 + tid);
    const float4 qc = __ldg(q4 + half4 + tid);

    double acc = 0.0;

    for (int rg = blockIdx.x; rg < Tb; rg += bpb) {
        const int row0 = rg * RPB;
        const float4* base4 = (const float4*)(dij + ((size_t)b * N + row0) * (size_t)N);

        float qi[RPB];
#pragma unroll
        for (int r = 0; r < RPB; r++) qi[r] = __ldg(qb + row0 + r);

        float acc0 = 0.0f, acc1 = 0.0f;

#pragma unroll
        for (int h = 0; h < RPB; h += 4) {
            const float4* r0 = base4 + (size_t)(h + 0) * (N >> 2);
            const float4* r1 = base4 + (size_t)(h + 1) * (N >> 2);
            const float4* r2 = base4 + (size_t)(h + 2) * (N >> 2);
            const float4* r3 = base4 + (size_t)(h + 3) * (N >> 2);

            // 8 fully-coalesced LDG.128, front-batched
            float4 da0 = __ldcs(r0 + tid);
            float4 dc0 = __ldcs(r0 + half4 + tid);
            float4 da1 = __ldcs(r1 + tid);
            float4 dc1 = __ldcs(r1 + half4 + tid);
            float4 da2 = __ldcs(r2 + tid);
            float4 dc2 = __ldcs(r2 + half4 + tid);
            float4 da3 = __ldcs(r3 + tid);
            float4 dc3 = __ldcs(r3 + half4 + tid);

            float l0 = __fdividef(qa.x, da0.x) + __fdividef(qa.y, da0.y)
                     + __fdividef(qa.z, da0.z) + __fdividef(qa.w, da0.w)
                     + __fdividef(qc.x, dc0.x) + __fdividef(qc.y, dc0.y)
                     + __fdividef(qc.z, dc0.z) + __fdividef(qc.w, dc0.w);
            acc0 = fmaf(qi[h + 0], l0, acc0);

            float l1 = __fdividef(qa.x, da1.x) + __fdividef(qa.y, da1.y)
                     + __fdividef(qa.z, da1.z) + __fdividef(qa.w, da1.w)
                     + __fdividef(qc.x, dc1.x) + __fdividef(qc.y, dc1.y)
                     + __fdividef(qc.z, dc1.z) + __fdividef(qc.w, dc1.w);
            acc1 = fmaf(qi[h + 1], l1, acc1);

            float l2 = __fdividef(qa.x, da2.x) + __fdividef(qa.y, da2.y)
                     + __fdividef(qa.z, da2.z) + __fdividef(qa.w, da2.w)
                     + __fdividef(qc.x, dc2.x) + __fdividef(qc.y, dc2.y)
                     + __fdividef(qc.z, dc2.z) + __fdividef(qc.w, dc2.w);
            acc0 = fmaf(qi[h + 2], l2, acc0);

            float l3 = __fdividef(qa.x, da3.x) + __fdividef(qa.y, da3.y)
                     + __fdividef(qa.z, da3.z) + __fdividef(qa.w, da3.w)
                     + __fdividef(qc.x, dc3.x) + __fdividef(qc.y, dc3.y)
                     + __fdividef(qc.z, dc3.z) + __fdividef(qc.w, dc3.w);
            acc1 = fmaf(qi[h + 3], l3, acc1);
        }

        acc += (double)acc0 + (double)acc1;   // promote once per tile
    }

    // block reduce (fp64)
    #pragma unroll
    for (int off = 16; off; off >>= 1)
        acc += __shfl_down_sync(0xffffffffu, acc, off);

    __shared__ double sm[THREADS / 32];
    __shared__ bool is_last;
    if ((tid & 31) == 0) sm[tid >> 5] = acc;
    __syncthreads();

    if (tid < 32) {
        double v = (tid < THREADS / 32) ? sm[tid] : 0.0;
        #pragma unroll
        for (int off = 4; off; off >>= 1)
            v += __shfl_down_sync(0xffffffffu, v, off);
        if (tid == 0) {
            atomicAdd(&g_sum[b], v);
            __threadfence();
            unsigned int ticket = atomicInc(&g_done, totalBlocks - 1);
            is_last = (ticket == totalBlocks - 1);
        }
    }
    __syncthreads();

    if (is_last && tid < B) {
        double total = atomicAdd(&g_sum[tid], 0.0);   // coherent read
        out[tid] = (float)(CCONST * total);
        g_sum[tid] = 0.0;                             // reset for next replay
    }
}

extern "C" void kernel_launch(void* const* d_in, const int* in_sizes, int n_in,
                              void* d_out, int out_size) {
    // Identify inputs by element count: largest = d_ij [B,N,N]; q = [B,N].
    int di = 0;
    for (int i = 1; i < n_in; i++)
        if (in_sizes[i] > in_sizes[di]) di = i;
    const float* dij = (const float*)d_in[di];

    const long long B = (out_size > 0) ? out_size : 16;
    int qi = (di == 0 && n_in > 1) ? 1 : 0;
    for (int i = 0; i < n_in; i++) {
        if (i == di) continue;
        long long nq = in_sizes[i];
        long long Nc = nq / B;
        if (Nc > 0 && B * Nc * Nc == (long long)in_sizes[di]) { qi = i; break; }
    }
    const float* q = (const float*)d_in[qi];

    const int N = (int)((long long)in_sizes[qi] / B);   // 2048

    int sm_count = 148;
    cudaDeviceGetAttribute(&sm_count, cudaDevAttrMultiProcessorCount, 0);

    int bpb = (sm_count * 4) / (int)B;                  // 152*4/16 = 38
    if (bpb < 1) bpb = 1;
    const int Tb = N / RPB;
    if (bpb > Tb) bpb = Tb;

    const unsigned int totalBlocks = (unsigned int)(bpb * B);
    dim3 grid(bpb, (unsigned)B);
    coulomb_coal<<<grid, THREADS>>>(dij, q, (float*)d_out, N, (int)B, totalBlocks);
}